// round 17
// baseline (speedup 1.0000x reference)
#include <cuda_runtime.h>
#include <cuda_fp16.h>

#define B_SZ    512
#define FEATS   30
#define NNZ     (B_SZ * FEATS)
#define FT_OUT  512
#define N_FEAT  40960
#define N_VFEAT 640
#define KPAIRS  (FT_OUT / 2)    // 256

// Packed indices, feature-major: g_packed[f*B + b] = stm_col | (nstm_col<<16)
__device__ unsigned g_packed[NNZ];
__device__ __half   g_vals[NNZ];          // values, feature-major, fp16
// Atomic output accumulator [b] and completion ticket (zeroed by prepass).
__device__ float    g_acc[B_SZ];
__device__ unsigned g_ticket;

// Dynamic smem: __half2 sft2[N_FEAT] (pair-interleaved fused table, 160 KB),
//               __half2 sfft2[N_VFEAT] (2.5 KB)
#define SMEM_BYTES ((N_FEAT + N_VFEAT) * 4)

static __device__ __forceinline__ unsigned h2u(__half2 h) {
    return *reinterpret_cast<unsigned*>(&h);
}
static __device__ __forceinline__ __half2 u2h(unsigned u) {
    return *reinterpret_cast<__half2*>(&u);
}

// 256-bit L2::evict_last load (the only width sm_103 allows the hint on).
// Biases L2 replacement so ft_w (80 MB < 126 MB L2) stays resident ACROSS
// graph replays — steady-state streaming then hits L2, not DRAM.
static __device__ __forceinline__ void ldg_el256(const float* p,
                                                 uint4& lo, uint4& hi) {
    asm("ld.global.nc.L2::evict_last.v8.b32 {%0,%1,%2,%3,%4,%5,%6,%7}, [%8];"
        : "=r"(lo.x), "=r"(lo.y), "=r"(lo.z), "=r"(lo.w),
          "=r"(hi.x), "=r"(hi.y), "=r"(hi.z), "=r"(hi.w)
        : "l"(p));
}

// ---------------------------------------------------------------------------
// Kernel 0: prepass. Pack cols into u32, values into fp16, feature-major.
// Zeroes the output accumulator and ticket. Triggers PDL completion
// immediately so the main kernel starts streaming ft_w concurrently.
// ---------------------------------------------------------------------------
__global__ void __launch_bounds__(256) pack_idx_kernel(
    const int*   __restrict__ stm_idx,    // [2, NNZ]; cols at offset NNZ
    const int*   __restrict__ nstm_idx,   // [2, NNZ]
    const float* __restrict__ values)     // [NNZ]
{
    cudaTriggerProgrammaticLaunchCompletion();

    const int e = blockIdx.x * 256 + threadIdx.x;
    if (e < B_SZ) g_acc[e] = 0.0f;
    if (e == 0)   g_ticket = 0u;
    if (e >= NNZ) return;

    const int b = e / FEATS;
    const int f = e % FEATS;
    const unsigned cs = (unsigned)stm_idx [NNZ + e];
    const unsigned cn = (unsigned)nstm_idx[NNZ + e];
    const int dst = f * B_SZ + b;
    g_packed[dst] = cs | (cn << 16);
    g_vals[dst]   = __float2half(values[e]);
}

// ---------------------------------------------------------------------------
// Kernel 1: one CTA per k-PAIR (256 CTAs, 512 threads, 1 CTA/SM, 163KB smem).
// Phase A: fft_w rows {k0, k0+1} -> smem, pair-interleaved half2.
// Phase B: stream ft_w rows {k0, k0+1} with 256-bit L2::evict_last loads
//          (replay-resident); sft2[c] = (ft[k0][c]+fft[k0][c%640],
//          ft[k1][c]+fft[k1][c%640]) pair-interleaved half2.
// (PDL grid sync before Phase C.)
// Phase C: thread t = batch row t; one random LDS.32 serves BOTH k's.
// Tail   : fold both k contributions into ONE float, atomicAdd to g_acc[t];
//          last-ticket CTA applies out_b + sigmoid and stores out.
// ---------------------------------------------------------------------------
__global__ void __launch_bounds__(512, 1) halfkp_pair_kernel(
    const float* __restrict__ ft_w,      // [512, 40960]
    const float* __restrict__ ft_b,      // [512]
    const float* __restrict__ fft_w,     // [512, 640]
    const float* __restrict__ fft_b,     // [512]
    const float* __restrict__ out_w,     // [1, 1024]
    const float* __restrict__ out_b,     // [1]
    float*       __restrict__ out)       // [512]
{
    extern __shared__ char smem_raw[];
    __half2* sft2  = reinterpret_cast<__half2*>(smem_raw);   // [N_FEAT]
    __half2* sfft2 = sft2 + N_FEAT;                          // [N_VFEAT]

    const int kp = blockIdx.x;
    const int k0 = 2 * kp;
    const int t  = threadIdx.x;

    // ---- Phase A: fft rows pair-interleaved (tiny; plain __ldg) ----
    if (t < N_VFEAT / 4) {   // 160 threads, one float4 per row each
        float4 a = __ldg(reinterpret_cast<const float4*>(
                             fft_w + (size_t)k0 * N_VFEAT) + t);
        float4 b = __ldg(reinterpret_cast<const float4*>(
                             fft_w + (size_t)(k0 + 1) * N_VFEAT) + t);
        uint4 p;
        p.x = h2u(__floats2half2_rn(a.x, b.x));
        p.y = h2u(__floats2half2_rn(a.y, b.y));
        p.z = h2u(__floats2half2_rn(a.z, b.z));
        p.w = h2u(__floats2half2_rn(a.w, b.w));
        reinterpret_cast<uint4*>(sfft2)[t] = p;
    }
    __syncthreads();

    // ---- Phase B: 256-bit evict-last streams, fuse fft, store pairs ----
    {
        const float* r0 = ft_w + (size_t)k0 * N_FEAT;
        const float* r1 = ft_w + (size_t)(k0 + 1) * N_FEAT;
        #pragma unroll
        for (int i = 0; i < N_FEAT / 8 / 512; i++) {     // 10 iterations
            const int idx = t + i * 512;                  // 32B-granule index
            const int c   = idx * 8;                      // half2 column base
            const int m   = c % N_VFEAT;                  // multiple of 8
            uint4 lo0, hi0, lo1, hi1;
            ldg_el256(r0 + (size_t)idx * 8, lo0, hi0);
            ldg_el256(r1 + (size_t)idx * 8, lo1, hi1);
            const uint4 fA = *reinterpret_cast<const uint4*>(sfft2 + m);
            const uint4 fB = *reinterpret_cast<const uint4*>(sfft2 + m + 4);
            uint4 pA, pB;
            pA.x = h2u(__hadd2(__floats2half2_rn(__uint_as_float(lo0.x),
                                                 __uint_as_float(lo1.x)), u2h(fA.x)));
            pA.y = h2u(__hadd2(__floats2half2_rn(__uint_as_float(lo0.y),
                                                 __uint_as_float(lo1.y)), u2h(fA.y)));
            pA.z = h2u(__hadd2(__floats2half2_rn(__uint_as_float(lo0.z),
                                                 __uint_as_float(lo1.z)), u2h(fA.z)));
            pA.w = h2u(__hadd2(__floats2half2_rn(__uint_as_float(lo0.w),
                                                 __uint_as_float(lo1.w)), u2h(fA.w)));
            pB.x = h2u(__hadd2(__floats2half2_rn(__uint_as_float(hi0.x),
                                                 __uint_as_float(hi1.x)), u2h(fB.x)));
            pB.y = h2u(__hadd2(__floats2half2_rn(__uint_as_float(hi0.y),
                                                 __uint_as_float(hi1.y)), u2h(fB.y)));
            pB.z = h2u(__hadd2(__floats2half2_rn(__uint_as_float(hi0.z),
                                                 __uint_as_float(hi1.z)), u2h(fB.z)));
            pB.w = h2u(__hadd2(__floats2half2_rn(__uint_as_float(hi0.w),
                                                 __uint_as_float(hi1.w)), u2h(fB.w)));
            *reinterpret_cast<uint4*>(sft2 + c)     = pA; // STS.128 x2
            *reinterpret_cast<uint4*>(sft2 + c + 4) = pB;
        }
    }
    __syncthreads();

    // PDL: packed index data (and zeroed g_acc) visible before Phase C.
    cudaGridDependencySynchronize();

    // ---- Phase C: thread t = batch row t; one LDS.32 serves both k's ----
    float2 accs = make_float2(0.f, 0.f);
    float2 accn = make_float2(0.f, 0.f);

    #pragma unroll
    for (int c = 0; c < 3; c++) {                         // chunks of 10
        unsigned p[10];
        __half   v[10];
        #pragma unroll
        for (int f = 0; f < 10; f++) {
            const int idx = (c * 10 + f) * B_SZ + t;      // lane-consecutive
            p[f] = __ldg(g_packed + idx);
            v[f] = g_vals[idx];
        }
        #pragma unroll
        for (int f = 0; f < 10; f++) {
            const float vf = __half2float(v[f]);
            float2 ws = __half22float2(sft2[p[f] & 0xFFFFu]);
            float2 wn = __half22float2(sft2[p[f] >> 16]);
            accs.x = fmaf(vf, ws.x, accs.x);
            accs.y = fmaf(vf, ws.y, accs.y);
            accn.x = fmaf(vf, wn.x, accn.x);
            accn.y = fmaf(vf, wn.y, accn.y);
        }
    }

    // ---- Epilogue: bias + clip + out_w; both k's folded into one float ----
    const float b0 = __ldg(ft_b + k0)     + __ldg(fft_b + k0);
    const float b1 = __ldg(ft_b + k0 + 1) + __ldg(fft_b + k0 + 1);
    const float w0 = __ldg(out_w + k0);
    const float w1 = __ldg(out_w + k0 + 1);
    const float u0 = __ldg(out_w + FT_OUT + k0);
    const float u1 = __ldg(out_w + FT_OUT + k0 + 1);

    const float part = w0 * __saturatef(accs.x + b0)
                     + u0 * __saturatef(accn.x + b0)
                     + w1 * __saturatef(accs.y + b1)
                     + u1 * __saturatef(accn.y + b1);

    atomicAdd(&g_acc[t], part);           // spread addresses, L2-resident

    // ---- Tail: last-ticket CTA applies sigmoid and writes the output ----
    __threadfence();                       // order adds before ticket
    __shared__ unsigned s_tick;
    if (t == 0) s_tick = atomicAdd(&g_ticket, 1u);
    __syncthreads();

    if (s_tick == KPAIRS - 1) {            // last CTA to finish
        if (t == 0) {
            while (atomicAdd(&g_ticket, 0u) < KPAIRS) { __nanosleep(32); }
        }
        __syncthreads();                   // all 256 CTAs' adds visible
        const float ob = __ldg(out_b);
        const float s  = *((volatile float*)&g_acc[t]);
        out[t] = 1.0f / (1.0f + expf(-(s + ob)));
    }
}

// ---------------------------------------------------------------------------
extern "C" void kernel_launch(void* const* d_in, const int* in_sizes, int n_in,
                              void* d_out, int out_size) {
    const int*   stm_idx  = (const int*)  d_in[0];
    const int*   nstm_idx = (const int*)  d_in[1];
    const float* values   = (const float*)d_in[2];
    const float* ft_w     = (const float*)d_in[3];
    const float* ft_b     = (const float*)d_in[4];
    const float* fft_w    = (const float*)d_in[5];
    const float* fft_b    = (const float*)d_in[6];
    const float* out_w    = (const float*)d_in[7];
    const float* out_b    = (const float*)d_in[8];
    float*       out      = (float*)d_out;

    (void)in_sizes; (void)n_in; (void)out_size;

    cudaFuncSetAttribute(halfkp_pair_kernel,
                         cudaFuncAttributeMaxDynamicSharedMemorySize, SMEM_BYTES);

    pack_idx_kernel<<<(NNZ + 255) / 256, 256>>>(stm_idx, nstm_idx, values);

    // Main kernel with PDL: overlaps with the pack kernel; the final
    // sigmoid runs in the last-finishing CTA (no reduce kernel at all).
    {
        cudaLaunchConfig_t cfg = {};
        cfg.gridDim          = dim3(KPAIRS);
        cfg.blockDim         = dim3(512);
        cfg.dynamicSmemBytes = SMEM_BYTES;
        cfg.stream           = 0;
        cudaLaunchAttribute at[1];
        at[0].id = cudaLaunchAttributeProgrammaticStreamSerialization;
        at[0].val.programmaticStreamSerializationAllowed = 1;
        cfg.attrs    = at;
        cfg.numAttrs = 1;
        cudaLaunchKernelEx(&cfg, halfkp_pair_kernel,
                           ft_w, ft_b, fft_w, fft_b, out_w, out_b, out);
    }
}